// round 5
// baseline (speedup 1.0000x reference)
#include <cuda_runtime.h>
#include <math.h>

#define H    512
#define S    65
#define NB   296
#define NT   256
#define RP   68                 // padded row stride
#define HSP  (512*RP)           // 34816 padded [h][s] matrix
#define ULL  unsigned long long

// ------------------------- scratch (device globals) -------------------------
__device__ float g_y[HSP];             // current y [512][68]
__device__ float g_P[8][9][HSP];       // kqv partials [kz][mat]
__device__ float g_Lp[8][3][65*RP];    // logits partials [hcc][slot]
__device__ float g_C[S*1536];          // concat buffer [65][1536]
__device__ float g_lp[24][HSP];        // linear partials [cc]
__device__ float g_zp[8][1024];
__device__ float g_t[512];
__device__ unsigned long long g_bar[24];

// ------------------------- packed f32x2 helpers -----------------------------
#define FMA2(acc, a, b) asm("fma.rn.f32x2 %0, %1, %2, %0;" : "+l"(acc) : "l"(a), "l"(b))
#define PACK2(d, x)     asm("mov.b64 %0, {%1, %1};" : "=l"(d) : "f"(x))
#define UNPK2(lo, hi, v) asm("mov.b64 {%0, %1}, %2;" : "=f"(lo), "=f"(hi) : "l"(v))

// ------------------------- device-wide barrier (release/acquire) -------------
__device__ __forceinline__ void gbar(int k) {
    __syncthreads();
    if (threadIdx.x == 0) {
        unsigned long long* p = &g_bar[k];
        unsigned long long old, cur;
        asm volatile("atom.release.gpu.add.u64 %0, [%1], 1;"
                     : "=l"(old) : "l"(p) : "memory");
        unsigned long long target = old - (old % (unsigned long long)NB)
                                  + (unsigned long long)NB;
        do {
            asm volatile("ld.acquire.gpu.u64 %0, [%1];"
                         : "=l"(cur) : "l"(p) : "memory");
        } while (cur < target);
    }
    __syncthreads();
}

// shared pool (floats): GEMM A0[1056] A1[1056] B0[1088] B1[1088] Tr[4352] = 8640
// LOGITS Ks[4352] Qs[4352] Sm[4420] = 13124 ; ATT Ls[4420] Vs[2176] = 6596
#define SMEM_F 13124

// =============================================================================
// GEMM item: out[m,s] = sum_k A[m,k]*B[k,s].  m-tile 64, k-chunk 16.
// modes: 0 = B from g_y (padded), 1 = linear (A col-access, B from g_C), 2 = emb*x
// lane -> m {lane, lane+32}; warp w(0..7) -> s {8w..8w+7}; w0 also s=64.
// =============================================================================
__device__ __forceinline__ void gemm_prefetch(const float* __restrict__ A,
        int mbase, int kb, int mode, const float* __restrict__ emb,
        const float* __restrict__ inp, float a4[4], float b5[5]) {
    const int tid = threadIdx.x;
    if (mode == 1) {
        int k = tid >> 6, m = tid & 63;
#pragma unroll
        for (int r = 0; r < 4; r++)
            a4[r] = A[(kb + k + 4 * r) * 512 + mbase + m];
        int s = tid >> 4, c = tid & 15;
#pragma unroll
        for (int r = 0; r < 4; r++)
            b5[r] = __ldcg(&g_C[(s + 16 * r) * 1536 + kb + c]);
        b5[4] = (tid < 16) ? __ldcg(&g_C[64 * 1536 + kb + tid]) : 0.f;
    } else {
        int m = tid >> 4, k = tid & 15;
#pragma unroll
        for (int r = 0; r < 4; r++)
            a4[r] = A[(mbase + m + 16 * r) * 512 + kb + k];
        if (mode == 0) {
#pragma unroll
            for (int r = 0; r < 4; r++) {
                int j = tid + 256 * r;
                b5[r] = __ldcg(&g_y[(kb + j / 65) * RP + j % 65]);
            }
            b5[4] = (tid < 16) ? __ldcg(&g_y[(kb + 15) * RP + 49 + tid]) : 0.f;
        } else {
#pragma unroll
            for (int r = 0; r < 4; r++) {
                int j = tid + 256 * r;
                int s = j % 65;
                float x = (s < 64) ? __ldg(&inp[s]) : 1.0f;
                b5[r] = emb[(kb + j / 65) * 65 + s] * x;
            }
            if (tid < 16) {
                int s = 49 + tid;
                float x = (s < 64) ? __ldg(&inp[s]) : 1.0f;
                b5[4] = emb[(kb + 15) * 65 + s] * x;
            } else b5[4] = 0.f;
        }
    }
}

__device__ __forceinline__ void gemm_store(float* At, float* Bs, int mode,
        const float a4[4], const float b5[5]) {
    const int tid = threadIdx.x;
    if (mode == 1) {
        int k = tid >> 6, m = tid & 63;
#pragma unroll
        for (int r = 0; r < 4; r++) At[(k + 4 * r) * 66 + m] = a4[r];
        int s = tid >> 4, c = tid & 15;
#pragma unroll
        for (int r = 0; r < 4; r++) Bs[c * RP + s + 16 * r] = b5[r];
        if (tid < 16) Bs[tid * RP + 64] = b5[4];
    } else {
        int m = tid >> 4, k = tid & 15;
#pragma unroll
        for (int r = 0; r < 4; r++) At[k * 66 + m + 16 * r] = a4[r];
#pragma unroll
        for (int r = 0; r < 4; r++) {
            int j = tid + 256 * r;
            Bs[(j / 65) * RP + j % 65] = b5[r];
        }
        if (tid < 16) Bs[15 * RP + 49 + tid] = b5[4];
    }
}

__device__ __forceinline__ void gemm_item(float* sm, const float* __restrict__ A,
        int mbase, int kb0, int nch, int mode, const float* __restrict__ emb,
        const float* __restrict__ inp, float* __restrict__ outp) {
    const int tid = threadIdx.x, lane = tid & 31, w = tid >> 5;
    float* Ab0 = sm;          float* Ab1 = sm + 1056;
    float* Bb0 = sm + 2112;   float* Bb1 = sm + 3200;
    float* Tr  = sm + 4288;   // [64][68]

    float a4[4], b5[5];
    gemm_prefetch(A, mbase, kb0, mode, emb, inp, a4, b5);
    gemm_store(Ab0, Bb0, mode, a4, b5);
    __syncthreads();

    ULL acc[2][4];
#pragma unroll
    for (int i = 0; i < 2; i++)
#pragma unroll
        for (int j = 0; j < 4; j++) acc[i][j] = 0;
    float t0 = 0.f, t1 = 0.f;

    for (int c = 0; c < nch; c++) {
        if (c + 1 < nch)
            gemm_prefetch(A, mbase, kb0 + (c + 1) * 16, mode, emb, inp, a4, b5);
        float* At = (c & 1) ? Ab1 : Ab0;
        float* Bs = (c & 1) ? Bb1 : Bb0;
        const float* Bw = Bs + (w << 3);
#pragma unroll
        for (int k = 0; k < 16; k++) {
            float x0 = At[k * 66 + lane];
            float x1 = At[k * 66 + 32 + lane];
            ULL pa0, pa1;
            PACK2(pa0, x0); PACK2(pa1, x1);
            ulonglong2 ba = *(const ulonglong2*)(Bw + k * RP);
            ulonglong2 bb = *(const ulonglong2*)(Bw + k * RP + 4);
            FMA2(acc[0][0], pa0, ba.x); FMA2(acc[0][1], pa0, ba.y);
            FMA2(acc[0][2], pa0, bb.x); FMA2(acc[0][3], pa0, bb.y);
            FMA2(acc[1][0], pa1, ba.x); FMA2(acc[1][1], pa1, ba.y);
            FMA2(acc[1][2], pa1, bb.x); FMA2(acc[1][3], pa1, bb.y);
            if (w == 0) {
                float b64 = Bs[k * RP + 64];
                t0 = fmaf(x0, b64, t0);
                t1 = fmaf(x1, b64, t1);
            }
        }
        if (c + 1 < nch) {
            gemm_store((c & 1) ? Ab0 : Ab1, (c & 1) ? Bb0 : Bb1, mode, a4, b5);
            __syncthreads();
        }
    }
    // stage to Tr (vector stores, 16B aligned thanks to pad 68)
    *(ulonglong2*)(Tr + lane * RP + 8 * w)       = make_ulonglong2(acc[0][0], acc[0][1]);
    *(ulonglong2*)(Tr + lane * RP + 8 * w + 4)   = make_ulonglong2(acc[0][2], acc[0][3]);
    *(ulonglong2*)(Tr + (lane + 32) * RP + 8 * w)     = make_ulonglong2(acc[1][0], acc[1][1]);
    *(ulonglong2*)(Tr + (lane + 32) * RP + 8 * w + 4) = make_ulonglong2(acc[1][2], acc[1][3]);
    if (w == 0) { Tr[lane * RP + 64] = t0; Tr[(lane + 32) * RP + 64] = t1; }
    __syncthreads();
    for (int i = tid; i < 64 * RP; i += NT)
        outp[mbase * RP + i] = Tr[i];
}

// ------------------------- kqv phase ----------------------------------------
__device__ void phase_kqv(float* sm, const float* __restrict__ wK,
                          const float* __restrict__ wQ, const float* __restrict__ wV,
                          int layer, const float* __restrict__ emb,
                          const float* __restrict__ inp) {
    const int nmats = (layer == 1) ? 9 : 3;
    const int nkz   = (layer == 1) ? 4 : 8;
    const int kspan = 512 / nkz;
    const int nch   = kspan / 16;
    const int per   = nmats * 8;
    const int items = per * nkz;
    const int mode  = (layer == 1) ? 2 : 0;
    for (int it = blockIdx.x; it < items; it += NB) {
        int kz = it / per, rem = it - kz * per;
        int mat = rem >> 3, mtile = rem & 7;
        int type = (layer == 1) ? (mat % 3) : mat;
        int head = (layer == 1) ? (mat / 3) : 2;
        const float* A = ((type == 0) ? wK : (type == 1) ? wQ : wV) + head * 262144;
        gemm_item(sm, A, mtile * 64, kz * kspan, nch, mode, emb, inp, &g_P[kz][mat][0]);
    }
}

// ------------------------- linear phase -------------------------------------
__device__ void phase_linear(float* sm, const float* __restrict__ W) {
    for (int it = blockIdx.x; it < 192; it += NB) {
        int cc = it >> 3, mtile = it & 7;
        gemm_item(sm, W, mtile * 64, cc * 64, 4, 1, 0, 0, &g_lp[cc][0]);
    }
}

// ------------------------- logits phase (h-chunk 64) ------------------------
__device__ void phase_logits(float* sm, int layer) {
    float* Ks = sm;            // [64][68]
    float* Qs = sm + 4352;
    float* Sm = sm + 8704;     // [65][68]
    const int tid = threadIdx.x, lane = tid & 31, w = tid >> 5;
    const int slots = (layer == 1) ? 3 : 1;
    const int nz    = (layer == 1) ? 4 : 8;
    const int items = slots * 8;
    for (int it = blockIdx.x; it < items; it += NB) {
        int slot = it >> 3, hcc = it & 7, h0 = hcc * 64;
        int matK = (layer == 1) ? slot * 3 : 0;
        int matQ = matK + 1;
        __syncthreads();
        for (int i = tid; i < 4352; i += NT) {
            float kv = 0.f, qv = 0.f;
            for (int z = 0; z < nz; z++) {
                kv += __ldcg(&g_P[z][matK][h0 * RP + i]);
                qv += __ldcg(&g_P[z][matQ][h0 * RP + i]);
            }
            Ks[i] = kv; Qs[i] = qv;
        }
        if (tid < 65) { Sm[tid * RP + 65] = 0.f; Sm[tid * RP + 66] = 0.f; Sm[tid * RP + 67] = 0.f; }
        __syncthreads();
        ULL r0[4] = {0,0,0,0}, r1[4] = {0,0,0,0}, r2[4] = {0,0,0,0};
        float u0 = 0.f, u1 = 0.f, u2 = 0.f;
        for (int h = 0; h < 64; h++) {
            float k0 = Ks[h * RP + lane];
            float k1 = Ks[h * RP + 32 + lane];
            float k2 = Ks[h * RP + 64];
            ULL p0, p1, p2;
            PACK2(p0, k0); PACK2(p1, k1); PACK2(p2, k2);
            ulonglong2 qa = *(const ulonglong2*)(Qs + h * RP + 8 * w);
            ulonglong2 qb = *(const ulonglong2*)(Qs + h * RP + 8 * w + 4);
            FMA2(r0[0], p0, qa.x); FMA2(r0[1], p0, qa.y);
            FMA2(r0[2], p0, qb.x); FMA2(r0[3], p0, qb.y);
            FMA2(r1[0], p1, qa.x); FMA2(r1[1], p1, qa.y);
            FMA2(r1[2], p1, qb.x); FMA2(r1[3], p1, qb.y);
            FMA2(r2[0], p2, qa.x); FMA2(r2[1], p2, qa.y);
            FMA2(r2[2], p2, qb.x); FMA2(r2[3], p2, qb.y);
            if (w == 0) {
                float q64 = Qs[h * RP + 64];
                u0 = fmaf(k0, q64, u0); u1 = fmaf(k1, q64, u1); u2 = fmaf(k2, q64, u2);
            }
        }
        *(ulonglong2*)(Sm + lane * RP + 8 * w)     = make_ulonglong2(r0[0], r0[1]);
        *(ulonglong2*)(Sm + lane * RP + 8 * w + 4) = make_ulonglong2(r0[2], r0[3]);
        *(ulonglong2*)(Sm + (lane + 32) * RP + 8 * w)     = make_ulonglong2(r1[0], r1[1]);
        *(ulonglong2*)(Sm + (lane + 32) * RP + 8 * w + 4) = make_ulonglong2(r1[2], r1[3]);
        if (lane == 0) {
            *(ulonglong2*)(Sm + 64 * RP + 8 * w)     = make_ulonglong2(r2[0], r2[1]);
            *(ulonglong2*)(Sm + 64 * RP + 8 * w + 4) = make_ulonglong2(r2[2], r2[3]);
        }
        if (w == 0) {
            Sm[lane * RP + 64] = u0;
            Sm[(lane + 32) * RP + 64] = u1;
            if (lane == 0) Sm[64 * RP + 64] = u2;
        }
        __syncthreads();
        float* Lp = &g_Lp[hcc][slot][0];
        for (int i = tid; i < 65 * RP; i += NT) Lp[i] = Sm[i];
    }
}

// ------------------------- att phase (softmax fused, h-chunk 32) ------------
__device__ void phase_att(float* sm, int layer) {
    float* Ls = sm;            // [65][68]
    float* Vs = sm + 4420;     // [32][68]
    const int tid = threadIdx.x, lane = tid & 31, w = tid >> 5;
    const int slots = (layer == 1) ? 3 : 1;
    const int nz    = (layer == 1) ? 4 : 8;
    const int items = slots * 16;
    for (int it = blockIdx.x; it < items; it += NB) {
        int slot = it >> 4, hc = it & 15, h0 = hc * 32;
        int matV = (layer == 1) ? slot * 3 + 2 : 2;
        int col0 = (layer == 1) ? slot * 512 : 1024;
        __syncthreads();
        for (int i = tid; i < 65 * RP; i += NT) {
            float v = 0.f;
#pragma unroll
            for (int c = 0; c < 8; c++) v += __ldcg(&g_Lp[c][slot][i]);
            Ls[i] = v;
        }
        for (int i = tid; i < 32 * RP; i += NT) {
            float v = 0.f;
            for (int z = 0; z < nz; z++) v += __ldcg(&g_P[z][matV][h0 * RP + i]);
            Vs[i] = v;
        }
        if (tid < 32) { Vs[tid * RP + 65] = 0.f; Vs[tid * RP + 66] = 0.f; Vs[tid * RP + 67] = 0.f; }
        __syncthreads();
        for (int a = w; a < 65; a += 8) {
            float e0 = Ls[a * RP + lane];
            float e1 = Ls[a * RP + 32 + lane];
            float e2 = (lane == 0) ? Ls[a * RP + 64] : -3.0e38f;
            float mx = fmaxf(e0, fmaxf(e1, e2));
#pragma unroll
            for (int off = 16; off > 0; off >>= 1)
                mx = fmaxf(mx, __shfl_xor_sync(0xffffffffu, mx, off));
            float x0 = expf(e0 - mx);
            float x1 = expf(e1 - mx);
            float x2 = (lane == 0) ? expf(e2 - mx) : 0.f;
            float ssum = x0 + x1 + x2;
#pragma unroll
            for (int off = 16; off > 0; off >>= 1)
                ssum += __shfl_xor_sync(0xffffffffu, ssum, off);
            float inv = 1.0f / ssum;
            Ls[a * RP + lane] = x0 * inv;
            Ls[a * RP + 32 + lane] = x1 * inv;
            if (lane == 0) Ls[a * RP + 64] = x2 * inv;
        }
        __syncthreads();
        ULL acc[8] = {0,0,0,0,0,0,0,0};
        ULL acc64 = 0;
        const float* Vrow = Vs + lane * RP;
        for (int p = 0; p < 34; p++) {
            ULL vv = *(const ULL*)(Vrow + 2 * p);
#pragma unroll
            for (int j = 0; j < 8; j++) {
                ULL lp = *(const ULL*)(Ls + (8 * w + j) * RP + 2 * p);
                FMA2(acc[j], lp, vv);
            }
            if (w == 0) {
                ULL l64 = *(const ULL*)(Ls + 64 * RP + 2 * p);
                FMA2(acc64, l64, vv);
            }
        }
#pragma unroll
        for (int j = 0; j < 8; j++) {
            float lo, hi; UNPK2(lo, hi, acc[j]);
            g_C[(8 * w + j) * 1536 + col0 + h0 + lane] = lo + hi;
        }
        if (w == 0) {
            float lo, hi; UNPK2(lo, hi, acc64);
            g_C[64 * 1536 + col0 + h0 + lane] = lo + hi;
        }
    }
}

// ------------------------- reduce + relu -> g_y ------------------------------
__device__ void phase_rr() {
    for (int i = blockIdx.x * NT + threadIdx.x; i < HSP; i += NB * NT) {
        float v = 0.f;
#pragma unroll
        for (int c = 0; c < 24; c++) v += __ldcg(&g_lp[c][i]);
        g_y[i] = fmaxf(v, 0.f);
    }
}

// ------------------------- final chain --------------------------------------
__device__ void phase_fc1(float* sm, const float* __restrict__ W3) {   // [1536][1024]
    float* Crs = sm;           // [192]
    float* Rs  = sm + 192;     // [256]
    const int tid = threadIdx.x;
    for (int it = blockIdx.x; it < 64; it += NB) {
        int jt = it & 7, cc = it >> 3;
        int c0 = cc * 192, j0 = jt * 128;
        __syncthreads();
        for (int i = tid; i < 192; i += NT)
            Crs[i] = __ldcg(&g_C[64 * 1536 + c0 + i]);
        __syncthreads();
        int j = j0 + (tid & 127);
        int q = tid >> 7;   // 0..1
        float acc = 0.f;
        for (int c = q * 96; c < q * 96 + 96; c++)
            acc = fmaf(Crs[c], W3[(c0 + c) * 1024 + j], acc);
        Rs[tid] = acc;
        __syncthreads();
        if (tid < 128) g_zp[cc][j0 + tid] = Rs[tid] + Rs[tid + 128];
    }
}

__device__ void phase_ft(float* sm, const float* __restrict__ W4) {   // [1024][512]
    float* zs = sm;            // [1024]
    float* Rs = sm + 1024;     // [8][128]
    const int tid = threadIdx.x, lane = tid & 31, w = tid >> 5;
    for (int it = blockIdx.x; it < 4; it += NB) {
        int h0 = it * 128;
        __syncthreads();
        for (int i = tid; i < 1024; i += NT) {
            float v = 0.f;
#pragma unroll
            for (int c = 0; c < 8; c++) v += __ldcg(&g_zp[c][i]);
            zs[i] = fmaxf(v, 0.f);
        }
        __syncthreads();
        int hh = h0 + lane * 4;
        float4 a = make_float4(0.f, 0.f, 0.f, 0.f);
        for (int k = w * 128; k < w * 128 + 128; k++) {
            float zv = zs[k];
            float4 wr = *(const float4*)(&W4[k * 512 + hh]);
            a.x = fmaf(zv, wr.x, a.x); a.y = fmaf(zv, wr.y, a.y);
            a.z = fmaf(zv, wr.z, a.z); a.w = fmaf(zv, wr.w, a.w);
        }
        Rs[w * 128 + lane * 4 + 0] = a.x;
        Rs[w * 128 + lane * 4 + 1] = a.y;
        Rs[w * 128 + lane * 4 + 2] = a.z;
        Rs[w * 128 + lane * 4 + 3] = a.w;
        __syncthreads();
        if (tid < 128) {
            float s = 0.f;
#pragma unroll
            for (int ww = 0; ww < 8; ww++) s += Rs[ww * 128 + tid];
            g_t[h0 + tid] = tanhf(s);
        }
    }
}

__device__ void phase_fout(float* sm, const float* __restrict__ W5,
                           float* __restrict__ out) {   // [512][64]
    float* ts = sm;            // [512]
    float* Rs = sm + 512;      // [8][64]
    const int tid = threadIdx.x, lane = tid & 31, w = tid >> 5;
    for (int i = tid; i < 512; i += NT) ts[i] = __ldcg(&g_t[i]);
    __syncthreads();
    float acc0 = 0.f, acc1 = 0.f;
    for (int k = w * 64; k < w * 64 + 64; k++) {
        float tv = ts[k];
        acc0 = fmaf(tv, W5[k * 64 + lane], acc0);
        acc1 = fmaf(tv, W5[k * 64 + 32 + lane], acc1);
    }
    Rs[w * 64 + lane] = acc0;
    Rs[w * 64 + 32 + lane] = acc1;
    __syncthreads();
    if (tid < 64) {
        float s = 0.f;
#pragma unroll
        for (int ww = 0; ww < 8; ww++) s += Rs[ww * 64 + tid];
        out[tid] = s;
    }
}

// =============================================================================
__global__ __launch_bounds__(NT, 2)
void persist_kernel(const float* __restrict__ inp, const float* __restrict__ emb,
                    const float* __restrict__ wk, const float* __restrict__ wq,
                    const float* __restrict__ wv,
                    const float* __restrict__ l1, const float* __restrict__ l2,
                    const float* __restrict__ l3, const float* __restrict__ l4,
                    const float* __restrict__ l5, float* __restrict__ out) {
    __shared__ __align__(16) float sm[SMEM_F];
    const int HH = 512 * 512 * 3;

    // ---- layer 1 ----
    phase_kqv(sm, wk, wq, wv, 1, emb, inp);          gbar(0);
    phase_logits(sm, 1);                             gbar(1);
    phase_att(sm, 1);                                gbar(2);
    phase_linear(sm, l1);                            gbar(3);
    phase_rr();                                      gbar(4);
    // ---- layer 2 ----
    phase_kqv(sm, wk + HH, wq + HH, wv + HH, 2, emb, inp);  gbar(5);
    phase_logits(sm, 2);                             gbar(6);
    phase_att(sm, 2);                                gbar(7);
    phase_linear(sm, l2);                            gbar(8);
    phase_rr();                                      gbar(9);
    // ---- layer 3 ----
    phase_kqv(sm, wk + 2 * HH, wq + 2 * HH, wv + 2 * HH, 3, emb, inp);  gbar(10);
    phase_logits(sm, 3);                             gbar(11);
    phase_att(sm, 3);                                gbar(12);
    // ---- final chain ----
    phase_fc1(sm, l3);                               gbar(13);
    phase_ft(sm, l4);                                gbar(14);
    if (blockIdx.x == 0) phase_fout(sm, l5, out);
}

// ------------------------- launcher ----------------------------------------
extern "C" void kernel_launch(void* const* d_in, const int* in_sizes, int n_in,
                              void* d_out, int out_size) {
    const float *inp = 0, *emb = 0, *l3 = 0, *l4 = 0, *l5 = 0;
    const float *tri[3] = {0, 0, 0};  int ntri = 0;
    const float *pr[2]  = {0, 0};     int npr  = 0;
    for (int i = 0; i < n_in; i++) {
        const float* p = (const float*)d_in[i];
        switch (in_sizes[i]) {
            case 64:      inp = p; break;
            case 33280:   emb = p; break;
            case 2359296: if (ntri < 3) tri[ntri++] = p; break;
            case 786432:  if (npr  < 2) pr[npr++]   = p; break;
            case 1572864: l3 = p; break;
            case 524288:  l4 = p; break;
            case 32768:   l5 = p; break;
            default: break;
        }
    }
    const float *wq, *wk, *wv;
    if (n_in > 0 && in_sizes[0] == 33280) { wk = tri[0]; wq = tri[1]; wv = tri[2]; }
    else                                  { wq = tri[0]; wk = tri[1]; wv = tri[2]; }
    const float *l1 = pr[0], *l2 = pr[1];
    float* out = (float*)d_out;

    persist_kernel<<<NB, NT>>>(inp, emb, wk, wq, wv, l1, l2, l3, l4, l5, out);
}

// round 6
// speedup vs baseline: 1.2032x; 1.2032x over previous
#include <cuda_runtime.h>
#include <math.h>

#define H    512
#define S    65
#define NB   296
#define NT   256
#define RP   68                 // padded row stride
#define HSP  (512*RP)           // 34816 padded [h][s] matrix
#define ULL  unsigned long long

// ------------------------- scratch (device globals) -------------------------
__device__ float g_y[HSP];             // current y [512][68]
__device__ float g_P[8][9][HSP];       // kqv partials [kz][mat]; reduced into [0][mat]
__device__ float g_Lp[8][3][65*RP];    // logits partials [hcc][slot]; reduced into [0][slot]
__device__ float g_C[S*1536];          // concat buffer [65][1536]
__device__ float g_lp[24][HSP];        // linear partials [cc]
__device__ float g_zp[8][1024];
__device__ float g_t[512];
__device__ unsigned long long g_bar[24];

// ------------------------- packed f32x2 helpers -----------------------------
#define FMA2(acc, a, b) asm("fma.rn.f32x2 %0, %1, %2, %0;" : "+l"(acc) : "l"(a), "l"(b))
#define PACK2(d, x)     asm("mov.b64 %0, {%1, %1};" : "=l"(d) : "f"(x))
#define UNPK2(lo, hi, v) asm("mov.b64 {%0, %1}, %2;" : "=f"(lo), "=f"(hi) : "l"(v))

// ------------------------- device-wide barrier ------------------------------
__device__ __forceinline__ void gbar(int k) {
    __threadfence();
    __syncthreads();
    if (threadIdx.x == 0) {
        unsigned long long* p = &g_bar[k];
        unsigned long long old, cur;
        asm volatile("atom.release.gpu.add.u64 %0, [%1], 1;"
                     : "=l"(old) : "l"(p) : "memory");
        unsigned long long target = old - (old % (unsigned long long)NB)
                                  + (unsigned long long)NB;
        do {
            asm volatile("ld.acquire.gpu.u64 %0, [%1];"
                         : "=l"(cur) : "l"(p) : "memory");
        } while (cur < target);
    }
    __syncthreads();
}

// ------------------------- L2 prefetch --------------------------------------
__device__ __forceinline__ void pf_range(const float* p, int nfloat) {
    int lines = nfloat >> 5;    // 128B lines
    for (int i = blockIdx.x * NT + threadIdx.x; i < lines; i += NB * NT)
        asm volatile("prefetch.global.L2 [%0];" :: "l"(p + (i << 5)));
}

// shared pool (floats): GEMM A0[1056] A1[1056] B0[1088] B1[1088] Tr[4352] = 8640
// LOGITS Ks[4352] Qs[4352] Sm[4420] = 13124 ; ATT Ls[4420] Vs[2176] = 6596
#define SMEM_F 13124

// =============================================================================
// GEMM item: out[m,s] = sum_k A[m,k]*B[k,s].  m-tile 64, k-chunk 16.
// MODE: 0 = B from g_y (padded), 1 = linear (A col-access, B from g_C), 2 = emb*x
// lane -> m {lane, lane+32}; warp w(0..7) -> s {8w..8w+7}; w0 also s=64.
// =============================================================================
template<int MODE>
__device__ __forceinline__ void gemm_prefetch(const float* __restrict__ A,
        int mbase, int kb, const float* __restrict__ emb,
        const float* __restrict__ inp, float a4[4], float b5[5]) {
    const int tid = threadIdx.x;
    if (MODE == 1) {
        int k = tid >> 6, m = tid & 63;
#pragma unroll
        for (int r = 0; r < 4; r++)
            a4[r] = A[(kb + k + 4 * r) * 512 + mbase + m];
        int s = tid >> 4, c = tid & 15;
#pragma unroll
        for (int r = 0; r < 4; r++)
            b5[r] = __ldcg(&g_C[(s + 16 * r) * 1536 + kb + c]);
        b5[4] = (tid < 16) ? __ldcg(&g_C[64 * 1536 + kb + tid]) : 0.f;
    } else {
        int m = tid >> 4, k = tid & 15;
#pragma unroll
        for (int r = 0; r < 4; r++)
            a4[r] = A[(mbase + m + 16 * r) * 512 + kb + k];
        if (MODE == 0) {
#pragma unroll
            for (int r = 0; r < 4; r++) {
                int j = tid + 256 * r;
                b5[r] = __ldcg(&g_y[(kb + j / 65) * RP + j % 65]);
            }
            b5[4] = (tid < 16) ? __ldcg(&g_y[(kb + 15) * RP + 49 + tid]) : 0.f;
        } else {
#pragma unroll
            for (int r = 0; r < 4; r++) {
                int j = tid + 256 * r;
                int s = j % 65;
                float x = (s < 64) ? __ldg(&inp[s]) : 1.0f;
                b5[r] = emb[(kb + j / 65) * 65 + s] * x;
            }
            if (tid < 16) {
                int s = 49 + tid;
                float x = (s < 64) ? __ldg(&inp[s]) : 1.0f;
                b5[4] = emb[(kb + 15) * 65 + s] * x;
            } else b5[4] = 0.f;
        }
    }
}

template<int MODE>
__device__ __forceinline__ void gemm_store(float* At, float* Bs,
        const float a4[4], const float b5[5]) {
    const int tid = threadIdx.x;
    if (MODE == 1) {
        int k = tid >> 6, m = tid & 63;
#pragma unroll
        for (int r = 0; r < 4; r++) At[(k + 4 * r) * 66 + m] = a4[r];
        int s = tid >> 4, c = tid & 15;
#pragma unroll
        for (int r = 0; r < 4; r++) Bs[c * RP + s + 16 * r] = b5[r];
        if (tid < 16) Bs[tid * RP + 64] = b5[4];
    } else {
        int m = tid >> 4, k = tid & 15;
#pragma unroll
        for (int r = 0; r < 4; r++) At[k * 66 + m + 16 * r] = a4[r];
#pragma unroll
        for (int r = 0; r < 4; r++) {
            int j = tid + 256 * r;
            Bs[(j / 65) * RP + j % 65] = b5[r];
        }
        if (tid < 16) Bs[15 * RP + 49 + tid] = b5[4];
    }
}

template<int NCH, int MODE>
__device__ __forceinline__ void gemm_item(float* sm, const float* __restrict__ A,
        int mbase, int kb0, const float* __restrict__ emb,
        const float* __restrict__ inp, float* __restrict__ outp) {
    const int tid = threadIdx.x, lane = tid & 31, w = tid >> 5;
    float* Ab0 = sm;          float* Ab1 = sm + 1056;
    float* Bb0 = sm + 2112;   float* Bb1 = sm + 3200;
    float* Tr  = sm + 4288;   // [64][68]

    float a4[4], b5[5];
    gemm_prefetch<MODE>(A, mbase, kb0, emb, inp, a4, b5);
    gemm_store<MODE>(Ab0, Bb0, a4, b5);
    __syncthreads();

    ULL acc[2][4];
#pragma unroll
    for (int i = 0; i < 2; i++)
#pragma unroll
        for (int j = 0; j < 4; j++) acc[i][j] = 0;
    float t0 = 0.f, t1 = 0.f;

#pragma unroll
    for (int c = 0; c < NCH; c++) {
        if (c + 1 < NCH)
            gemm_prefetch<MODE>(A, mbase, kb0 + (c + 1) * 16, emb, inp, a4, b5);
        float* At = (c & 1) ? Ab1 : Ab0;
        float* Bs = (c & 1) ? Bb1 : Bb0;
        const float* Bw = Bs + (w << 3);
#pragma unroll
        for (int k = 0; k < 16; k++) {
            float x0 = At[k * 66 + lane];
            float x1 = At[k * 66 + 32 + lane];
            ULL pa0, pa1;
            PACK2(pa0, x0); PACK2(pa1, x1);
            ulonglong2 ba = *(const ulonglong2*)(Bw + k * RP);
            ulonglong2 bb = *(const ulonglong2*)(Bw + k * RP + 4);
            FMA2(acc[0][0], pa0, ba.x); FMA2(acc[0][1], pa0, ba.y);
            FMA2(acc[0][2], pa0, bb.x); FMA2(acc[0][3], pa0, bb.y);
            FMA2(acc[1][0], pa1, ba.x); FMA2(acc[1][1], pa1, ba.y);
            FMA2(acc[1][2], pa1, bb.x); FMA2(acc[1][3], pa1, bb.y);
            if (w == 0) {
                float b64 = Bs[k * RP + 64];
                t0 = fmaf(x0, b64, t0);
                t1 = fmaf(x1, b64, t1);
            }
        }
        if (c + 1 < NCH) {
            gemm_store<MODE>((c & 1) ? Ab0 : Ab1, (c & 1) ? Bb0 : Bb1, a4, b5);
            __syncthreads();
        }
    }
    *(ulonglong2*)(Tr + lane * RP + 8 * w)       = make_ulonglong2(acc[0][0], acc[0][1]);
    *(ulonglong2*)(Tr + lane * RP + 8 * w + 4)   = make_ulonglong2(acc[0][2], acc[0][3]);
    *(ulonglong2*)(Tr + (lane + 32) * RP + 8 * w)     = make_ulonglong2(acc[1][0], acc[1][1]);
    *(ulonglong2*)(Tr + (lane + 32) * RP + 8 * w + 4) = make_ulonglong2(acc[1][2], acc[1][3]);
    if (w == 0) { Tr[lane * RP + 64] = t0; Tr[(lane + 32) * RP + 64] = t1; }
    __syncthreads();
    for (int i = tid; i < 64 * RP; i += NT)
        outp[mbase * RP + i] = Tr[i];
}

// ------------------------- kqv phase ----------------------------------------
template<int LAYER>
__device__ void phase_kqv(float* sm, const float* __restrict__ wK,
                          const float* __restrict__ wQ, const float* __restrict__ wV,
                          const float* __restrict__ emb, const float* __restrict__ inp) {
    constexpr int nmats = (LAYER == 1) ? 9 : 3;
    constexpr int nkz   = (LAYER == 1) ? 4 : 8;
    constexpr int kspan = 512 / nkz;
    constexpr int per   = nmats * 8;
    constexpr int items = per * nkz;
    for (int it = blockIdx.x; it < items; it += NB) {
        int kz = it / per, rem = it - kz * per;
        int mat = rem >> 3, mtile = rem & 7;
        int type = (LAYER == 1) ? (mat % 3) : mat;
        int head = (LAYER == 1) ? (mat / 3) : 2;
        const float* A = ((type == 0) ? wK : (type == 1) ? wQ : wV) + head * 262144;
        if (LAYER == 1)
            gemm_item<kspan/16, 2>(sm, A, mtile * 64, kz * kspan, emb, inp, &g_P[kz][mat][0]);
        else
            gemm_item<kspan/16, 0>(sm, A, mtile * 64, kz * kspan, emb, inp, &g_P[kz][mat][0]);
    }
}

// ------------------------- reduce kqv partials: g_P[0][mat] = sum_z ---------
template<int LAYER>
__device__ void phase_reduce() {
    constexpr int nmats = (LAYER == 1) ? 9 : 3;
    constexpr int nz    = (LAYER == 1) ? 4 : 8;
    constexpr int Q4    = HSP / 4;                 // 8704 float4 per matrix
    for (int j = blockIdx.x * NT + threadIdx.x; j < nmats * Q4; j += NB * NT) {
        int mat = j / Q4, i = j - mat * Q4;
        float4 v = __ldcg((const float4*)&g_P[0][mat][4 * i]);
#pragma unroll
        for (int z = 1; z < nz; z++) {
            float4 u = __ldcg((const float4*)&g_P[z][mat][4 * i]);
            v.x += u.x; v.y += u.y; v.z += u.z; v.w += u.w;
        }
        *(float4*)&g_P[0][mat][4 * i] = v;
    }
}

// ------------------------- logits phase (h-chunk 64) ------------------------
template<int LAYER>
__device__ void phase_logits(float* sm) {
    float* Ks = sm;            // [64][68]
    float* Qs = sm + 4352;
    float* Sm = sm + 8704;     // [65][68]
    const int tid = threadIdx.x, lane = tid & 31, w = tid >> 5;
    constexpr int slots = (LAYER == 1) ? 3 : 1;
    constexpr int items = slots * 8;
    for (int it = blockIdx.x; it < items; it += NB) {
        int slot = it >> 3, hcc = it & 7, h0 = hcc * 64;
        int matK = (LAYER == 1) ? slot * 3 : 0;
        int matQ = matK + 1;
        __syncthreads();
#pragma unroll 2
        for (int i = tid; i < 1088; i += NT) {   // 4352/4 float4s
            *(float4*)&Ks[4 * i] = __ldcg((const float4*)&g_P[0][matK][h0 * RP + 4 * i]);
            *(float4*)&Qs[4 * i] = __ldcg((const float4*)&g_P[0][matQ][h0 * RP + 4 * i]);
        }
        if (tid < 65) { Sm[tid * RP + 65] = 0.f; Sm[tid * RP + 66] = 0.f; Sm[tid * RP + 67] = 0.f; }
        __syncthreads();
        ULL r0[4] = {0,0,0,0}, r1[4] = {0,0,0,0}, r2[4] = {0,0,0,0};
        float u0 = 0.f, u1 = 0.f, u2 = 0.f;
        for (int h = 0; h < 64; h++) {
            float k0 = Ks[h * RP + lane];
            float k1 = Ks[h * RP + 32 + lane];
            float k2 = Ks[h * RP + 64];
            ULL p0, p1, p2;
            PACK2(p0, k0); PACK2(p1, k1); PACK2(p2, k2);
            ulonglong2 qa = *(const ulonglong2*)(Qs + h * RP + 8 * w);
            ulonglong2 qb = *(const ulonglong2*)(Qs + h * RP + 8 * w + 4);
            FMA2(r0[0], p0, qa.x); FMA2(r0[1], p0, qa.y);
            FMA2(r0[2], p0, qb.x); FMA2(r0[3], p0, qb.y);
            FMA2(r1[0], p1, qa.x); FMA2(r1[1], p1, qa.y);
            FMA2(r1[2], p1, qb.x); FMA2(r1[3], p1, qb.y);
            FMA2(r2[0], p2, qa.x); FMA2(r2[1], p2, qa.y);
            FMA2(r2[2], p2, qb.x); FMA2(r2[3], p2, qb.y);
            if (w == 0) {
                float q64 = Qs[h * RP + 64];
                u0 = fmaf(k0, q64, u0); u1 = fmaf(k1, q64, u1); u2 = fmaf(k2, q64, u2);
            }
        }
        *(ulonglong2*)(Sm + lane * RP + 8 * w)     = make_ulonglong2(r0[0], r0[1]);
        *(ulonglong2*)(Sm + lane * RP + 8 * w + 4) = make_ulonglong2(r0[2], r0[3]);
        *(ulonglong2*)(Sm + (lane + 32) * RP + 8 * w)     = make_ulonglong2(r1[0], r1[1]);
        *(ulonglong2*)(Sm + (lane + 32) * RP + 8 * w + 4) = make_ulonglong2(r1[2], r1[3]);
        if (lane == 0) {
            *(ulonglong2*)(Sm + 64 * RP + 8 * w)     = make_ulonglong2(r2[0], r2[1]);
            *(ulonglong2*)(Sm + 64 * RP + 8 * w + 4) = make_ulonglong2(r2[2], r2[3]);
        }
        if (w == 0) {
            Sm[lane * RP + 64] = u0;
            Sm[(lane + 32) * RP + 64] = u1;
            if (lane == 0) Sm[64 * RP + 64] = u2;
        }
        __syncthreads();
        float* Lp = &g_Lp[hcc][slot][0];
        for (int i = tid; i < 65 * RP; i += NT) Lp[i] = Sm[i];
    }
}

// ------------------------- reduce logits partials: g_Lp[0][slot] = sum_hcc --
template<int LAYER>
__device__ void phase_lred() {
    constexpr int slots = (LAYER == 1) ? 3 : 1;
    constexpr int Q4 = (65 * RP) / 4;      // 1105 float4
    for (int j = blockIdx.x * NT + threadIdx.x; j < slots * Q4; j += NB * NT) {
        int slot = j / Q4, i = j - slot * Q4;
        float4 v = __ldcg((const float4*)&g_Lp[0][slot][4 * i]);
#pragma unroll
        for (int c = 1; c < 8; c++) {
            float4 u = __ldcg((const float4*)&g_Lp[c][slot][4 * i]);
            v.x += u.x; v.y += u.y; v.z += u.z; v.w += u.w;
        }
        *(float4*)&g_Lp[0][slot][4 * i] = v;
    }
}

// ------------------------- att phase (softmax fused, h-chunk 32) ------------
template<int LAYER>
__device__ void phase_att(float* sm) {
    float* Ls = sm;            // [65][68]
    float* Vs = sm + 4420;     // [32][68]
    const int tid = threadIdx.x, lane = tid & 31, w = tid >> 5;
    constexpr int slots = (LAYER == 1) ? 3 : 1;
    constexpr int items = slots * 16;
    for (int it = blockIdx.x; it < items; it += NB) {
        int slot = it >> 4, hc = it & 15, h0 = hc * 32;
        int matV = (LAYER == 1) ? slot * 3 + 2 : 2;
        int col0 = (LAYER == 1) ? slot * 512 : 1024;
        __syncthreads();
#pragma unroll 2
        for (int i = tid; i < 1105; i += NT)
            *(float4*)&Ls[4 * i] = __ldcg((const float4*)&g_Lp[0][slot][4 * i]);
#pragma unroll 2
        for (int i = tid; i < 544; i += NT)
            *(float4*)&Vs[4 * i] = __ldcg((const float4*)&g_P[0][matV][h0 * RP + 4 * i]);
        __syncthreads();
        if (tid < 32) { Vs[tid * RP + 65] = 0.f; Vs[tid * RP + 66] = 0.f; Vs[tid * RP + 67] = 0.f; }
        __syncthreads();
        for (int a = w; a < 65; a += 8) {
            float e0 = Ls[a * RP + lane];
            float e1 = Ls[a * RP + 32 + lane];
            float e2 = (lane == 0) ? Ls[a * RP + 64] : -3.0e38f;
            float mx = fmaxf(e0, fmaxf(e1, e2));
#pragma unroll
            for (int off = 16; off > 0; off >>= 1)
                mx = fmaxf(mx, __shfl_xor_sync(0xffffffffu, mx, off));
            float x0 = expf(e0 - mx);
            float x1 = expf(e1 - mx);
            float x2 = (lane == 0) ? expf(e2 - mx) : 0.f;
            float ssum = x0 + x1 + x2;
#pragma unroll
            for (int off = 16; off > 0; off >>= 1)
                ssum += __shfl_xor_sync(0xffffffffu, ssum, off);
            float inv = 1.0f / ssum;
            Ls[a * RP + lane] = x0 * inv;
            Ls[a * RP + 32 + lane] = x1 * inv;
            if (lane == 0) Ls[a * RP + 64] = x2 * inv;
        }
        __syncthreads();
        ULL acc[8] = {0,0,0,0,0,0,0,0};
        ULL acc64 = 0;
        const float* Vrow = Vs + lane * RP;
        for (int p = 0; p < 34; p++) {
            ULL vv = *(const ULL*)(Vrow + 2 * p);
#pragma unroll
            for (int j = 0; j < 8; j++) {
                ULL lp = *(const ULL*)(Ls + (8 * w + j) * RP + 2 * p);
                FMA2(acc[j], lp, vv);
            }
            if (w == 0) {
                ULL l64 = *(const ULL*)(Ls + 64 * RP + 2 * p);
                FMA2(acc64, l64, vv);
            }
        }
#pragma unroll
        for (int j = 0; j < 8; j++) {
            float lo, hi; UNPK2(lo, hi, acc[j]);
            g_C[(8 * w + j) * 1536 + col0 + h0 + lane] = lo + hi;
        }
        if (w == 0) {
            float lo, hi; UNPK2(lo, hi, acc64);
            g_C[64 * 1536 + col0 + h0 + lane] = lo + hi;
        }
    }
}

// ------------------------- linear phase -------------------------------------
__device__ void phase_linear(float* sm, const float* __restrict__ W) {
    for (int it = blockIdx.x; it < 192; it += NB) {
        int cc = it >> 3, mtile = it & 7;
        gemm_item<4, 1>(sm, W, mtile * 64, cc * 64, 0, 0, &g_lp[cc][0]);
    }
}

// ------------------------- reduce + relu -> g_y ------------------------------
__device__ void phase_rr() {
    for (int j = blockIdx.x * NT + threadIdx.x; j < HSP / 4; j += NB * NT) {
        float4 v = __ldcg((const float4*)&g_lp[0][4 * j]);
#pragma unroll
        for (int c = 1; c < 24; c++) {
            float4 u = __ldcg((const float4*)&g_lp[c][4 * j]);
            v.x += u.x; v.y += u.y; v.z += u.z; v.w += u.w;
        }
        v.x = fmaxf(v.x, 0.f); v.y = fmaxf(v.y, 0.f);
        v.z = fmaxf(v.z, 0.f); v.w = fmaxf(v.w, 0.f);
        *(float4*)&g_y[4 * j] = v;
    }
}

// ------------------------- final chain --------------------------------------
__device__ void phase_fc1(float* sm, const float* __restrict__ W3) {   // [1536][1024]
    float* Crs = sm;           // [192]
    float* Rs  = sm + 192;     // [256]
    const int tid = threadIdx.x;
    for (int it = blockIdx.x; it < 64; it += NB) {
        int jt = it & 7, cc = it >> 3;
        int c0 = cc * 192, j0 = jt * 128;
        __syncthreads();
        for (int i = tid; i < 192; i += NT)
            Crs[i] = __ldcg(&g_C[64 * 1536 + c0 + i]);
        __syncthreads();
        int j = j0 + (tid & 127);
        int q = tid >> 7;
        float acc = 0.f;
#pragma unroll 4
        for (int c = q * 96; c < q * 96 + 96; c++)
            acc = fmaf(Crs[c], W3[(c0 + c) * 1024 + j], acc);
        Rs[tid] = acc;
        __syncthreads();
        if (tid < 128) g_zp[cc][j0 + tid] = Rs[tid] + Rs[tid + 128];
    }
}

__device__ void phase_ft(float* sm, const float* __restrict__ W4) {   // [1024][512]
    float* zs = sm;            // [1024]
    float* Rs = sm + 1024;     // [8][128]
    const int tid = threadIdx.x, lane = tid & 31, w = tid >> 5;
    for (int it = blockIdx.x; it < 4; it += NB) {
        int h0 = it * 128;
        __syncthreads();
        for (int i = tid; i < 1024; i += NT) {
            float v = 0.f;
#pragma unroll
            for (int c = 0; c < 8; c++) v += __ldcg(&g_zp[c][i]);
            zs[i] = fmaxf(v, 0.f);
        }
        __syncthreads();
        int hh = h0 + lane * 4;
        float4 a = make_float4(0.f, 0.f, 0.f, 0.f);
#pragma unroll 4
        for (int k = w * 128; k < w * 128 + 128; k++) {
            float zv = zs[k];
            float4 wr = *(const float4*)(&W4[k * 512 + hh]);
            a.x = fmaf(zv, wr.x, a.x); a.y = fmaf(zv, wr.y, a.y);
            a.z = fmaf(zv, wr.z, a.z); a.w = fmaf(zv, wr.w, a.w);
        }
        Rs[w * 128 + lane * 4 + 0] = a.x;
        Rs[w * 128 + lane * 4 + 1] = a.y;
        Rs[w * 128 + lane * 4 + 2] = a.z;
        Rs[w * 128 + lane * 4 + 3] = a.w;
        __syncthreads();
        if (tid < 128) {
            float s = 0.f;
#pragma unroll
            for (int ww = 0; ww < 8; ww++) s += Rs[ww * 128 + tid];
            g_t[h0 + tid] = tanhf(s);
        }
    }
}

__device__ void phase_fout(float* sm, const float* __restrict__ W5,
                           float* __restrict__ out) {   // [512][64]
    float* ts = sm;            // [512]
    float* Rs = sm + 512;      // [8][64]
    const int tid = threadIdx.x, lane = tid & 31, w = tid >> 5;
    for (int i = tid; i < 512; i += NT) ts[i] = __ldcg(&g_t[i]);
    __syncthreads();
    float acc0 = 0.f, acc1 = 0.f;
    for (int k = w * 64; k < w * 64 + 64; k++) {
        float tv = ts[k];
        acc0 = fmaf(tv, W5[k * 64 + lane], acc0);
        acc1 = fmaf(tv, W5[k * 64 + 32 + lane], acc1);
    }
    Rs[w * 64 + lane] = acc0;
    Rs[w * 64 + 32 + lane] = acc1;
    __syncthreads();
    if (tid < 64) {
        float s = 0.f;
#pragma unroll
        for (int ww = 0; ww < 8; ww++) s += Rs[ww * 64 + tid];
        out[tid] = s;
    }
}

// =============================================================================
__global__ __launch_bounds__(NT, 2)
void persist_kernel(const float* __restrict__ inp, const float* __restrict__ emb,
                    const float* __restrict__ wk, const float* __restrict__ wq,
                    const float* __restrict__ wv,
                    const float* __restrict__ l1, const float* __restrict__ l2,
                    const float* __restrict__ l3, const float* __restrict__ l4,
                    const float* __restrict__ l5, float* __restrict__ out) {
    __shared__ __align__(16) float sm[SMEM_F];
    const int HH = 512 * 512 * 3;

    // Warm L2 with every weight byte that will be touched (live ranges only).
    pf_range(wk, 786432); pf_range(wk + 1310720, 262144); pf_range(wk + 2097152, 262144);
    pf_range(wq, 786432); pf_range(wq + 1310720, 262144); pf_range(wq + 2097152, 262144);
    pf_range(wv, 786432); pf_range(wv + 1310720, 262144); pf_range(wv + 2097152, 262144);
    pf_range(l1, 786432); pf_range(l2, 786432);
    pf_range(l3, 1572864); pf_range(l4, 524288); pf_range(l5, 32768);
    pf_range(emb, 33280);

    // ---- layer 1 ----
    phase_kqv<1>(sm, wk, wq, wv, emb, inp);          gbar(0);
    phase_reduce<1>();                               gbar(1);
    phase_logits<1>(sm);                             gbar(2);
    phase_lred<1>();                                 gbar(3);
    phase_att<1>(sm);                                gbar(4);
    phase_linear(sm, l1);                            gbar(5);
    phase_rr();                                      gbar(6);
    // ---- layer 2 ----
    phase_kqv<2>(sm, wk + HH, wq + HH, wv + HH, emb, inp);  gbar(7);
    phase_reduce<2>();                               gbar(8);
    phase_logits<2>(sm);                             gbar(9);
    phase_lred<2>();                                 gbar(10);
    phase_att<2>(sm);                                gbar(11);
    phase_linear(sm, l2);                            gbar(12);
    phase_rr();                                      gbar(13);
    // ---- layer 3 ----
    phase_kqv<3>(sm, wk + 2 * HH, wq + 2 * HH, wv + 2 * HH, emb, inp);  gbar(14);
    phase_reduce<3>();                               gbar(15);
    phase_logits<3>(sm);                             gbar(16);
    phase_lred<3>();                                 gbar(17);
    phase_att<3>(sm);                                gbar(18);
    // ---- final chain ----
    phase_fc1(sm, l3);                               gbar(19);
    phase_ft(sm, l4);                                gbar(20);
    if (blockIdx.x == 0) phase_fout(sm, l5, out);
}

// ------------------------- launcher ----------------------------------------
extern "C" void kernel_launch(void* const* d_in, const int* in_sizes, int n_in,
                              void* d_out, int out_size) {
    const float *inp = 0, *emb = 0, *l3 = 0, *l4 = 0, *l5 = 0;
    const float *tri[3] = {0, 0, 0};  int ntri = 0;
    const float *pr[2]  = {0, 0};     int npr  = 0;
    for (int i = 0; i < n_in; i++) {
        const float* p = (const float*)d_in[i];
        switch (in_sizes[i]) {
            case 64:      inp = p; break;
            case 33280:   emb = p; break;
            case 2359296: if (ntri < 3) tri[ntri++] = p; break;
            case 786432:  if (npr  < 2) pr[npr++]   = p; break;
            case 1572864: l3 = p; break;
            case 524288:  l4 = p; break;
            case 32768:   l5 = p; break;
            default: break;
        }
    }
    const float *wq, *wk, *wv;
    if (n_in > 0 && in_sizes[0] == 33280) { wk = tri[0]; wq = tri[1]; wv = tri[2]; }
    else                                  { wq = tri[0]; wk = tri[1]; wv = tri[2]; }
    const float *l1 = pr[0], *l2 = pr[1];
    float* out = (float*)d_out;

    persist_kernel<<<NB, NT>>>(inp, emb, wk, wq, wv, l1, l2, l3, l4, l5, out);
}